// round 1
// baseline (speedup 1.0000x reference)
#include <cuda_runtime.h>
#include <math.h>

// FNetBlock: B=4, L=512, D=64, LAG=32.
// Math reduction: out[row,d] = b0 + c[row,d] * (c>0 ? A_pos[row] : A_neg[row])
//   c[row,d]  = sum_e x[row,e] cos(2*pi*d*e/64)
//   m[row,f]  = sum_j mask[row,j] cos(2*pi*f*j/512), f=0..256
//   s = sort(m); A_pos = sum_k W[k] s[k] + W[32+k] s[225+k]
//                A_neg = sum_k W[k] s[256-k] + W[32+k] s[31-k]
//
// DFT via j-fold (v[j]=u[j]+u[512-j]) and f-fold (m[f]=E+O, m[256-f]=E-O),
// cosines generated by a renormalized rotation recurrence (no tables).

#define NROWS 2048

__global__ __launch_bounds__(256) void fnet_kernel(
    const float* __restrict__ x,     // [2048, 64]
    const float* __restrict__ mask,  // [2048, 512]
    const float* __restrict__ W,     // [64]
    const float* __restrict__ bvec,  // [1]
    float* __restrict__ out)         // [2048, 64]
{
    __shared__ float  sb[2][512];    // mask row, then m values (+INF pad), then sorted
    __shared__ float2 vp[2][130];    // folded mask: .x = v[2a], .y = v[2a+1]
    __shared__ float  xs[2][64];
    __shared__ float  sA[2][2];      // [r][0]=A_pos, [r][1]=A_neg

    const int tid  = threadIdx.x;
    const int row0 = blockIdx.x * 2;

    // ---- load mask rows (coalesced) and x rows ----
    for (int i = tid; i < 1024; i += 256) {
        int r = i >> 9, j = i & 511;
        sb[r][j] = mask[(row0 + r) * 512 + j];
    }
    if (tid < 128) {
        xs[tid >> 6][tid & 63] = x[(row0 + (tid >> 6)) * 64 + (tid & 63)];
    }
    __syncthreads();

    // ---- fold: v[j] = u[j] + u[512-j] (j=1..255), v[0]=u[0], v[256]=u[256] ----
    for (int idx = tid; idx < 258; idx += 256) {
        int r = idx / 129, a = idx % 129;
        const float* u = sb[r];
        float ve = (a == 0) ? u[0] : ((a == 128) ? u[256] : (u[2 * a] + u[512 - 2 * a]));
        float vo = (a == 128) ? 0.0f : (u[2 * a + 1] + u[511 - 2 * a]);
        vp[r][a] = make_float2(ve, vo);
    }
    __syncthreads();

    // ---- main folded DFT: thread f in [0,128) per row ----
    {
        const int r = tid >> 7;
        const int f = tid & 127;
        float sphi, cphi, spsi, cpsi;
        sincospif((float)f * (1.0f / 128.0f), &sphi, &cphi); // phi = 2*pi*f/256
        sincospif((float)f * (1.0f / 256.0f), &spsi, &cpsi); // psi = pi*f/256

        float c = 1.0f, s = 0.0f;
        float E = 0.0f, P = 0.0f, Q = 0.0f;
        #pragma unroll 8
        for (int a = 0; a < 128; a++) {
            float2 v = vp[r][a];            // broadcast LDS.64
            E = fmaf(v.x, c, E);
            P = fmaf(v.y, c, P);
            Q = fmaf(v.y, s, Q);
            float t1 = s * sphi;
            float t2 = c * sphi;
            float cn = fmaf(c, cphi, -t1);
            float sn = fmaf(s, cphi,  t2);
            c = cn; s = sn;
            if ((a & 7) == 7) {             // renormalize to kill amplitude drift
                float n   = fmaf(c, c, s * s);
                float inv = fmaf(-0.5f, n, 1.5f);
                c *= inv; s *= inv;
            }
        }
        E = fmaf(vp[r][128].x, c, E);       // even tail a=128 (j=256)
        float O = fmaf(cpsi, P, -(spsi * Q));

        sb[r][f]       = E + O;             // m[f]
        sb[r][256 - f] = E - O;             // m[256-f]  (f=0 -> m[256])

        if (f == 127) {                     // m[128] = sum_a (-1)^a v[2a]
            float e = 0.0f;
            for (int a = 0; a <= 128; a++) {
                float vv = vp[r][a].x;
                e += (a & 1) ? -vv : vv;
            }
            sb[r][128] = e;
        }
        // pad [257,512) with +INF so ascending sort leaves real values in [0,257)
        for (int p = 257 + f; p < 512; p += 128)
            sb[r][p] = __int_as_float(0x7f800000);
    }

    // ---- 64-point cosine transform of x (independent of sort buffer) ----
    float cval = 0.0f;
    {
        const int r  = tid >> 7;
        const int tl = tid & 127;
        if (tl < 64) {
            float sph, cph;
            sincospif((float)tl * (1.0f / 32.0f), &sph, &cph); // 2*pi*d/64
            float c = 1.0f, s = 0.0f;
            #pragma unroll 8
            for (int e = 0; e < 64; e++) {
                cval = fmaf(xs[r][e], c, cval);
                float t1 = s * sph;
                float t2 = c * sph;
                float cn = fmaf(c, cph, -t1);
                float sn = fmaf(s, cph,  t2);
                c = cn; s = sn;
                if ((e & 7) == 7) {
                    float n   = fmaf(c, c, s * s);
                    float inv = fmaf(-0.5f, n, 1.5f);
                    c *= inv; s *= inv;
                }
            }
        }
    }

    // ---- bitonic sort (ascending), 512 elems per row, both rows in parallel ----
    for (int k = 2; k <= 512; k <<= 1) {
        for (int j = k >> 1; j > 0; j >>= 1) {
            __syncthreads();
            for (int idx = tid; idx < 1024; idx += 256) {
                int r = idx >> 9, i = idx & 511;
                int ixj = i ^ j;
                if (ixj > i) {
                    float va = sb[r][i];
                    float vb = sb[r][ixj];
                    bool up = ((i & k) == 0);
                    if ((va > vb) == up) { sb[r][i] = vb; sb[r][ixj] = va; }
                }
            }
        }
    }
    __syncthreads();

    // ---- epilogue: A_pos / A_neg (one warp per row) ----
    {
        const int r  = tid >> 7;
        const int tl = tid & 127;
        if (tl < 32) {
            int   k  = tl;
            float w1 = W[k], w2 = W[32 + k];
            float pp = fmaf(w1, sb[r][k],        w2 * sb[r][225 + k]);
            float pn = fmaf(w1, sb[r][256 - k],  w2 * sb[r][31 - k]);
            #pragma unroll
            for (int o = 16; o > 0; o >>= 1) {
                pp += __shfl_xor_sync(0xffffffffu, pp, o);
                pn += __shfl_xor_sync(0xffffffffu, pn, o);
            }
            if (k == 0) { sA[r][0] = pp; sA[r][1] = pn; }
        }
    }
    __syncthreads();

    // ---- output ----
    {
        const int r  = tid >> 7;
        const int tl = tid & 127;
        if (tl < 64) {
            float A  = (cval > 0.0f) ? sA[r][0] : sA[r][1];
            out[(row0 + r) * 64 + tl] = fmaf(cval, A, bvec[0]);
        }
    }
}

extern "C" void kernel_launch(void* const* d_in, const int* in_sizes, int n_in,
                              void* d_out, int out_size) {
    const float* x    = (const float*)d_in[0];
    const float* mask = (const float*)d_in[1];
    const float* W    = (const float*)d_in[2];
    const float* b    = (const float*)d_in[3];
    float* out = (float*)d_out;
    fnet_kernel<<<NROWS / 2, 256>>>(x, mask, W, b, out);
}

// round 2
// speedup vs baseline: 3.1265x; 3.1265x over previous
#include <cuda_runtime.h>
#include <math.h>

// FNetBlock: B=4, L=512, D=64, LAG=32  (2048 rows)
// out[row,d] = b0 + c[row,d] * (c>0 ? A_pos[row] : A_neg[row])
//   c[row,d] = sum_e x[row,e] cos(2*pi*d*e/64)
//   m[row,f] = sum_j mask[row,j] cos(2*pi*f*j/512), f=0..256
//   s = sort(m);  A_pos = sum_k W[k] s[k]      + W[32+k] s[225+k]
//                 A_neg = sum_k W[k] s[256-k]  + W[32+k] s[31-k]
// Only bottom-32 / top-32 of s are needed -> register bitonic selection.
// Cosines: Chebyshev recurrence (4 FFMA/iter), exact reseed every 32 steps.

__global__ __launch_bounds__(256) void fnet_kernel(
    const float* __restrict__ x,     // [2048, 64]
    const float* __restrict__ mask,  // [2048, 512]
    const float* __restrict__ W,     // [64]
    const float* __restrict__ bvec,  // [1]
    float* __restrict__ out)         // [2048, 64]
{
    __shared__ float  sb[2][512];     // mask rows
    __shared__ float2 vp[2][130];     // folded mask: .x=v[2a], .y=v[2a+1]
    __shared__ float  xs[2][64];
    __shared__ float  slow[2][4][32]; // per-warp sorted bottom-32
    __shared__ float  shigh[2][4][32];// per-warp sorted top-32
    __shared__ float  mbuf[2][4][32]; // level-1 merge results
    __shared__ float  sm128[2];
    __shared__ float  sPP[2][2], sPN[2][2];
    __shared__ float  s8[8];          // cos(pi*k/4)

    const int tid  = threadIdx.x;
    const int lane = tid & 31;
    const int r    = tid >> 7;        // row within block
    const int tl   = tid & 127;
    const int wr   = (tid >> 5) & 3;  // warp within row
    const int row0 = blockIdx.x * 2;

    if (tid < 8) {
        const float rt = 0.70710678118654752f;
        float v = (tid==0)?1.f:(tid==1)?rt:(tid==2)?0.f:(tid==3)?-rt:
                  (tid==4)?-1.f:(tid==5)?-rt:(tid==6)?0.f:rt;
        s8[tid] = v;
    }
    // coalesced vectorized loads
    {
        const float4* m4 = (const float4*)(mask + row0 * 512);
        ((float4*)&sb[0][0])[tid] = m4[tid];
    }
    if (tid < 32) {
        const float4* x4 = (const float4*)(x + row0 * 64);
        ((float4*)&xs[0][0])[tid] = x4[tid];
    }
    __syncthreads();

    // ---- fold: v[j] = u[j] + u[512-j] ----
    for (int idx = tid; idx < 258; idx += 256) {
        int rr = idx / 129, a = idx - rr * 129;
        const float* u = sb[rr];
        float ve, vo;
        if (a == 0)        { ve = u[0];   vo = u[1] + u[511]; }
        else if (a == 128) { ve = u[256]; vo = 0.f; }
        else               { ve = u[2*a] + u[512-2*a]; vo = u[2*a+1] + u[511-2*a]; }
        vp[rr][a] = make_float2(ve, vo);
    }
    __syncthreads();

    // ---- folded DFT, Chebyshev cosines, exact reseed every 32 ----
    const int f = tl;
    float cphi, sphi, cpsi, spsi;
    sincospif((float)f * (1.0f/128.0f), &sphi, &cphi);  // phi = 2*pi*f/256
    sincospif((float)f * (1.0f/256.0f), &spsi, &cpsi);  // psi = pi*f/256
    const float t = 2.0f * cphi;

    float cc = 1.0f,  cp = cphi;                        // cos(0), cos(-phi)
    float wc = cpsi,  wp = cpsi*cphi + spsi*sphi;       // cos(psi), cos(psi-phi)
    float E = 0.f, O = 0.f;
    const float2* vrow = vp[r];
    #pragma unroll 1
    for (int q = 0; q < 4; q++) {
        if (q) {  // exact reseed at a = 32q : 32q*phi = pi*f*q/4
            int k8 = (f * q) & 7;
            float c32 = s8[k8];
            float s32 = s8[(k8 + 6) & 7];
            cc = c32;
            cp = fmaf(c32, cphi, s32 * sphi);
            float sw = fmaf(s32, cpsi, c32 * spsi);
            wc = fmaf(c32, cpsi, -(s32 * spsi));
            wp = fmaf(wc, cphi, sw * sphi);
        }
        const int base = q * 32;
        #pragma unroll
        for (int a = 0; a < 32; a++) {
            float2 v = vrow[base + a];                  // LDS.64 broadcast
            E = fmaf(v.x, cc, E);
            O = fmaf(v.y, wc, O);
            float cn = fmaf(t, cc, -cp); cp = cc; cc = cn;
            float wn = fmaf(t, wc, -wp); wp = wc; wc = wn;
        }
    }
    E += (f & 1) ? -vrow[128].x : vrow[128].x;          // a=128 tail, cos(pi*f)=+-1
    float v0 = E + O;    // m[f]
    float v1 = E - O;    // m[256-f]

    // ---- m[128] = sum_a (-1)^a v_e[a], by warp 3 of each row ----
    if (wr == 3) {
        float acc = vrow[lane].x + vrow[lane+32].x + vrow[lane+64].x + vrow[lane+96].x;
        float s = (lane & 1) ? -acc : acc;
        if (lane == 0) s += vrow[128].x;
        #pragma unroll
        for (int o = 16; o; o >>= 1) s += __shfl_xor_sync(0xffffffffu, s, o);
        if (lane == 0) sm128[r] = s;
    }

    // ---- warp bitonic sort of 64 (2 regs/lane), ascending ----
    #pragma unroll
    for (int k = 2; k <= 32; k <<= 1) {
        #pragma unroll
        for (int j = k >> 1; j > 0; j >>= 1) {
            bool up0 = ((lane & k) == 0);
            bool up1 = (((lane + 32) & k) == 0);
            float p0 = __shfl_xor_sync(0xffffffffu, v0, j);
            float p1 = __shfl_xor_sync(0xffffffffu, v1, j);
            bool low = ((lane & j) == 0);
            v0 = (low == up0) ? fminf(v0, p0) : fmaxf(v0, p0);
            v1 = (low == up1) ? fminf(v1, p1) : fmaxf(v1, p1);
        }
    }
    {   // k = 64 stage: j=32 crosses regs, then clean
        float lo = fminf(v0, v1), hi = fmaxf(v0, v1);
        v0 = lo; v1 = hi;
        #pragma unroll
        for (int j = 16; j > 0; j >>= 1) {
            float p0 = __shfl_xor_sync(0xffffffffu, v0, j);
            float p1 = __shfl_xor_sync(0xffffffffu, v1, j);
            bool low = ((lane & j) == 0);
            v0 = low ? fminf(v0, p0) : fmaxf(v0, p0);
            v1 = low ? fminf(v1, p1) : fmaxf(v1, p1);
        }
    }
    slow [r][wr][lane] = v0;   // bottom 32 ascending
    shigh[r][wr][lane] = v1;   // top 32 ascending
    __syncthreads();

    // ---- level-1 merges (keep 32 extremes of 64) ----
    {
        float res;
        if      (wr == 0) res = fminf(slow [r][0][lane], slow [r][1][31-lane]);
        else if (wr == 1) res = fminf(slow [r][2][lane], slow [r][3][31-lane]);
        else if (wr == 2) res = fmaxf(shigh[r][0][lane], shigh[r][1][31-lane]);
        else              res = fmaxf(shigh[r][2][lane], shigh[r][3][31-lane]);
        #pragma unroll
        for (int j = 16; j > 0; j >>= 1) {   // bitonic clean -> ascending
            float p = __shfl_xor_sync(0xffffffffu, res, j);
            res = ((lane & j) == 0) ? fminf(res, p) : fmaxf(res, p);
        }
        mbuf[r][wr][lane] = res;
    }
    __syncthreads();

    // ---- final merges + m128 insert + epilogue dot  |  x-transform ----
    float cval = 0.f;
    if (wr == 0) {
        float lowv = fminf(mbuf[r][0][lane], mbuf[r][1][31-lane]);
        #pragma unroll
        for (int j = 16; j > 0; j >>= 1) {
            float p = __shfl_xor_sync(0xffffffffu, lowv, j);
            lowv = ((lane & j) == 0) ? fminf(lowv, p) : fmaxf(lowv, p);
        }
        float m128 = sm128[r];
        unsigned bal = __ballot_sync(0xffffffffu, lowv < m128);
        int cnt = __popc(bal);
        float sh = __shfl_up_sync(0xffffffffu, lowv, 1);
        if (lane >= cnt) lowv = (lane == cnt) ? m128 : sh;
        // partials: pp = W[k]*low[k], pn = W[63-k]*low[k]
        float pp = __ldg(&W[lane])      * lowv;
        float pn = __ldg(&W[63 - lane]) * lowv;
        #pragma unroll
        for (int o = 16; o; o >>= 1) {
            pp += __shfl_xor_sync(0xffffffffu, pp, o);
            pn += __shfl_xor_sync(0xffffffffu, pn, o);
        }
        if (lane == 0) { sPP[r][0] = pp; sPN[r][0] = pn; }
    } else if (wr == 1) {
        float highv = fmaxf(mbuf[r][2][lane], mbuf[r][3][31-lane]);
        #pragma unroll
        for (int j = 16; j > 0; j >>= 1) {
            float p = __shfl_xor_sync(0xffffffffu, highv, j);
            highv = ((lane & j) == 0) ? fminf(highv, p) : fmaxf(highv, p);
        }
        float m128 = sm128[r];
        unsigned bal = __ballot_sync(0xffffffffu, highv < m128);
        int cnt = __popc(bal);
        float shd = __shfl_down_sync(0xffffffffu, highv, 1);
        highv = (lane + 1 < cnt) ? shd : ((lane + 1 == cnt) ? m128 : highv);
        // partials: pp = W[32+k]*high[k], pn = W[31-k]*high[k]
        float pp = __ldg(&W[32 + lane]) * highv;
        float pn = __ldg(&W[31 - lane]) * highv;
        #pragma unroll
        for (int o = 16; o; o >>= 1) {
            pp += __shfl_xor_sync(0xffffffffu, pp, o);
            pn += __shfl_xor_sync(0xffffffffu, pn, o);
        }
        if (lane == 0) { sPP[r][1] = pp; sPN[r][1] = pn; }
    } else {
        // 64-point cosine transform of x, Chebyshev with exact reseed at 32
        int d = tl - 64;
        float cph, sph;
        sincospif((float)d * (1.0f/32.0f), &sph, &cph);  // 2*pi*d/64
        float td = 2.f * cph;
        float c0 = 1.f, c1m = cph;
        const float* xr = xs[r];
        #pragma unroll
        for (int e = 0; e < 32; e++) {
            cval = fmaf(xr[e], c0, cval);
            float cn = fmaf(td, c0, -c1m); c1m = c0; c0 = cn;
        }
        float sgn = (d & 1) ? -1.f : 1.f;                // cos(pi*d)
        c0 = sgn; c1m = sgn * cph;
        #pragma unroll
        for (int e = 32; e < 64; e++) {
            cval = fmaf(xr[e], c0, cval);
            float cn = fmaf(td, c0, -c1m); c1m = c0; c0 = cn;
        }
    }
    __syncthreads();

    // ---- output (warps 2,3 of each row; coalesced) ----
    if (wr >= 2) {
        int d = tl - 64;
        float Ap = sPP[r][0] + sPP[r][1];
        float An = sPN[r][0] + sPN[r][1];
        float A = (cval > 0.f) ? Ap : An;
        out[(row0 + r) * 64 + d] = fmaf(cval, A, bvec[0]);
    }
}

extern "C" void kernel_launch(void* const* d_in, const int* in_sizes, int n_in,
                              void* d_out, int out_size) {
    const float* x    = (const float*)d_in[0];
    const float* mask = (const float*)d_in[1];
    const float* W    = (const float*)d_in[2];
    const float* b    = (const float*)d_in[3];
    fnet_kernel<<<1024, 256>>>(x, mask, W, b, (float*)d_out);
}

// round 4
// speedup vs baseline: 4.0089x; 1.2822x over previous
#include <cuda_runtime.h>
#include <math.h>

// FNetBlock: B=4, L=512, D=64, LAG=32  (2048 rows)
// out[row,d] = b0 + c[row,d] * (c>0 ? A_pos[row] : A_neg[row])
//   c[row,d] = sum_e x[row,e] cos(2*pi*d*e/64)
//   m[row,f] = sum_j mask[row,j] cos(2*pi*f*j/512), f=0..256
//   s = sort(m);  A_pos = sum_k W[k] s[k]      + W[32+k] s[225+k]
//                 A_neg = sum_k W[k] s[256-k]  + W[32+k] s[31-k]
// Two radix-2 folds -> 64-term per-thread DFT (parity-dependent arrays).
// Cosines: Chebyshev recurrence (4 FFMA per 2 useful MACs), exact reseed at 32.
// Bottom-32/top-32 selection via register bitonic sort + merges.

__global__ __launch_bounds__(256) void fnet_kernel(
    const float* __restrict__ x,     // [2048, 64]
    const float* __restrict__ mask,  // [2048, 512]
    const float* __restrict__ W,     // [64]
    const float* __restrict__ bvec,  // [1]
    float* __restrict__ out)         // [2048, 64]
{
    __shared__ float  sb[2][512];       // mask rows (u)
    __shared__ float  fold4[2][64][4];  // (we+, wo+, we-, wo-) per a
    __shared__ float  xs[2][64];
    __shared__ float  slow[2][4][32];
    __shared__ float  shigh[2][4][32];
    __shared__ float  mbuf[2][4][32];
    __shared__ float  sm128[2];
    __shared__ float  sPP[2][2], sPN[2][2];
    __shared__ float  s8[8];            // cos(pi*k/4)

    const int tid  = threadIdx.x;
    const int lane = tid & 31;
    const int r    = tid >> 7;          // row within block
    const int tl   = tid & 127;
    const int wr   = (tid >> 5) & 3;    // warp within row
    const int row0 = blockIdx.x * 2;

    if (tid < 8) {
        const float rt = 0.70710678118654752f;
        float v = (tid==0)?1.f:(tid==1)?rt:(tid==2)?0.f:(tid==3)?-rt:
                  (tid==4)?-1.f:(tid==5)?-rt:(tid==6)?0.f:rt;
        s8[tid] = v;
    }
    // coalesced vectorized loads
    {
        const float4* m4 = (const float4*)(mask + row0 * 512);
        ((float4*)&sb[0][0])[tid] = m4[tid];
    }
    if (tid < 32) {
        const float4* x4 = (const float4*)(x + row0 * 64);
        ((float4*)&xs[0][0])[tid] = x4[tid];
    }
    __syncthreads();

    // ---- double fold: we_p[a], wo_p[a] for a=0..63, parity p ----
    // v_e[a] = u[2a]+u[512-2a]; v_o[a] = u[2a+1]+u[511-2a]
    // we_p[a] = v_e[a] + s*v_e[128-a]; wo_p[a] = v_o[a] + s*v_o[127-a]; s=(-1)^p
    {
        const int rr = tid >> 7;
        const int p  = (tid >> 6) & 1;
        const int a  = tid & 63;
        const float s = p ? -1.0f : 1.0f;
        const float* u = sb[rr];
        float we, wo;
        if (a == 0) {
            we = fmaf(s, u[256], u[0]);
            wo = (u[1] + u[511]) + s * (u[255] + u[257]);
        } else {
            we = (u[2*a] + u[512-2*a]) + s * (u[256-2*a] + u[256+2*a]);
            wo = (u[2*a+1] + u[511-2*a]) + s * (u[255-2*a] + u[257+2*a]);
        }
        *(float2*)&fold4[rr][a][2*p] = make_float2(we, wo);
    }
    __syncthreads();

    // ---- folded DFT: 64 iters, Chebyshev cosines, exact reseed at 32 ----
    const int f = tl;
    const int p = f & 1;
    float cphi, sphi, cpsi, spsi;
    sincospif((float)f * (1.0f/128.0f), &sphi, &cphi);  // phi = 2*pi*f/256
    sincospif((float)f * (1.0f/256.0f), &spsi, &cpsi);  // psi = pi*f/256
    const float t = 2.0f * cphi;

    float cc = 1.0f,  cp = cphi;                        // cos(a*phi), a=0; cos(-phi)
    float wc = cpsi,  wp = fmaf(cpsi, cphi, spsi * sphi); // cos(psi), cos(psi-phi)
    float E = 0.f, O = 0.f;
    const float2* wrow = ((const float2*)&fold4[r][0][0]) + p;  // stride 2 float2s
    #pragma unroll
    for (int a = 0; a < 32; a++) {
        float2 w = wrow[2*a];
        E = fmaf(w.x, cc, E);
        O = fmaf(w.y, wc, O);
        float cn = fmaf(t, cc, -cp); cp = cc; cc = cn;
        float wn = fmaf(t, wc, -wp); wp = wc; wc = wn;
    }
    {   // exact reseed at a=32: 32*phi = pi*f/4
        int k8 = f & 7;
        float c32 = s8[k8];
        float s32 = s8[(k8 + 6) & 7];
        cc = c32;
        cp = fmaf(c32, cphi, s32 * sphi);
        float sw = fmaf(s32, cpsi, c32 * spsi);
        wc = fmaf(c32, cpsi, -(s32 * spsi));
        wp = fmaf(wc, cphi, sw * sphi);
    }
    #pragma unroll
    for (int a = 32; a < 64; a++) {
        float2 w = wrow[2*a];
        E = fmaf(w.x, cc, E);
        O = fmaf(w.y, wc, O);
        float cn = fmaf(t, cc, -cp); cp = cc; cc = cn;
        float wn = fmaf(t, wc, -wp); wp = wc; wc = wn;
    }
    if (p == 0) {                      // tail: v_e[64]*cos(pi*f/2)
        float t64 = sb[r][128] + sb[r][384];
        E += (f & 2) ? -t64 : t64;
    }
    float v0 = E + O;    // m[f]
    float v1 = E - O;    // m[256-f]

    // ---- m[128] = sum_{b} u[4b] - u[4b+2], by warp 3 of each row ----
    if (wr == 3) {
        const float* u = sb[r];
        float s = 0.f;
        #pragma unroll
        for (int q = 0; q < 4; q++) {
            int b = lane + q * 32;
            s += u[4*b] - u[4*b+2];
        }
        #pragma unroll
        for (int o = 16; o; o >>= 1) s += __shfl_xor_sync(0xffffffffu, s, o);
        if (lane == 0) sm128[r] = s;
    }

    // ---- warp bitonic sort of 64 (2 regs/lane), ascending ----
    #pragma unroll
    for (int k = 2; k <= 32; k <<= 1) {
        #pragma unroll
        for (int j = k >> 1; j > 0; j >>= 1) {
            bool up0 = ((lane & k) == 0);
            bool up1 = (((lane + 32) & k) == 0);
            float p0 = __shfl_xor_sync(0xffffffffu, v0, j);
            float p1 = __shfl_xor_sync(0xffffffffu, v1, j);
            bool low = ((lane & j) == 0);
            v0 = (low == up0) ? fminf(v0, p0) : fmaxf(v0, p0);
            v1 = (low == up1) ? fminf(v1, p1) : fmaxf(v1, p1);
        }
    }
    {   // k = 64 stage: j=32 crosses regs, then clean
        float lo = fminf(v0, v1), hi = fmaxf(v0, v1);
        v0 = lo; v1 = hi;
        #pragma unroll
        for (int j = 16; j > 0; j >>= 1) {
            float p0 = __shfl_xor_sync(0xffffffffu, v0, j);
            float p1 = __shfl_xor_sync(0xffffffffu, v1, j);
            bool low = ((lane & j) == 0);
            v0 = low ? fminf(v0, p0) : fmaxf(v0, p0);
            v1 = low ? fminf(v1, p1) : fmaxf(v1, p1);
        }
    }
    slow [r][wr][lane] = v0;   // bottom 32 ascending
    shigh[r][wr][lane] = v1;   // top 32 ascending
    __syncthreads();

    // ---- level-1 merges (keep 32 extremes of 64) ----
    {
        float res;
        if      (wr == 0) res = fminf(slow [r][0][lane], slow [r][1][31-lane]);
        else if (wr == 1) res = fminf(slow [r][2][lane], slow [r][3][31-lane]);
        else if (wr == 2) res = fmaxf(shigh[r][0][lane], shigh[r][1][31-lane]);
        else              res = fmaxf(shigh[r][2][lane], shigh[r][3][31-lane]);
        #pragma unroll
        for (int j = 16; j > 0; j >>= 1) {   // bitonic clean -> ascending
            float pv = __shfl_xor_sync(0xffffffffu, res, j);
            res = ((lane & j) == 0) ? fminf(res, pv) : fmaxf(res, pv);
        }
        mbuf[r][wr][lane] = res;
    }
    __syncthreads();

    // ---- final merges + m128 insert + epilogue dot  |  x-transform ----
    float cval = 0.f;
    if (wr == 0) {
        float lowv = fminf(mbuf[r][0][lane], mbuf[r][1][31-lane]);
        #pragma unroll
        for (int j = 16; j > 0; j >>= 1) {
            float pv = __shfl_xor_sync(0xffffffffu, lowv, j);
            lowv = ((lane & j) == 0) ? fminf(lowv, pv) : fmaxf(lowv, pv);
        }
        float m128 = sm128[r];
        unsigned bal = __ballot_sync(0xffffffffu, lowv < m128);
        int cnt = __popc(bal);
        float sh = __shfl_up_sync(0xffffffffu, lowv, 1);
        if (lane >= cnt) lowv = (lane == cnt) ? m128 : sh;
        float pp = __ldg(&W[lane])      * lowv;
        float pn = __ldg(&W[63 - lane]) * lowv;
        #pragma unroll
        for (int o = 16; o; o >>= 1) {
            pp += __shfl_xor_sync(0xffffffffu, pp, o);
            pn += __shfl_xor_sync(0xffffffffu, pn, o);
        }
        if (lane == 0) { sPP[r][0] = pp; sPN[r][0] = pn; }
    } else if (wr == 1) {
        float highv = fmaxf(mbuf[r][2][lane], mbuf[r][3][31-lane]);
        #pragma unroll
        for (int j = 16; j > 0; j >>= 1) {
            float pv = __shfl_xor_sync(0xffffffffu, highv, j);
            highv = ((lane & j) == 0) ? fminf(highv, pv) : fmaxf(highv, pv);
        }
        float m128 = sm128[r];
        unsigned bal = __ballot_sync(0xffffffffu, highv < m128);
        int cnt = __popc(bal);
        float shd = __shfl_down_sync(0xffffffffu, highv, 1);
        highv = (lane + 1 < cnt) ? shd : ((lane + 1 == cnt) ? m128 : highv);
        float pp = __ldg(&W[32 + lane]) * highv;
        float pn = __ldg(&W[31 - lane]) * highv;
        #pragma unroll
        for (int o = 16; o; o >>= 1) {
            pp += __shfl_xor_sync(0xffffffffu, pp, o);
            pn += __shfl_xor_sync(0xffffffffu, pn, o);
        }
        if (lane == 0) { sPP[r][1] = pp; sPN[r][1] = pn; }
    } else {
        // 64-point cosine transform of x, Chebyshev with exact reseed at 32
        int d = tl - 64;
        float cph, sph;
        sincospif((float)d * (1.0f/32.0f), &sph, &cph);  // 2*pi*d/64
        float td = 2.f * cph;
        float c0 = 1.f, c1m = cph;
        const float* xr = xs[r];
        #pragma unroll
        for (int e = 0; e < 32; e++) {
            cval = fmaf(xr[e], c0, cval);
            float cn = fmaf(td, c0, -c1m); c1m = c0; c0 = cn;
        }
        float sgn = (d & 1) ? -1.f : 1.f;                // cos(pi*d)
        c0 = sgn; c1m = sgn * cph;
        #pragma unroll
        for (int e = 32; e < 64; e++) {
            cval = fmaf(xr[e], c0, cval);
            float cn = fmaf(td, c0, -c1m); c1m = c0; c0 = cn;
        }
    }
    __syncthreads();

    // ---- output (warps 2,3 of each row; coalesced) ----
    if (wr >= 2) {
        int d = tl - 64;
        float Ap = sPP[r][0] + sPP[r][1];
        float An = sPN[r][0] + sPN[r][1];
        float A = (cval > 0.f) ? Ap : An;
        out[(row0 + r) * 64 + d] = fmaf(cval, A, bvec[0]);
    }
}

extern "C" void kernel_launch(void* const* d_in, const int* in_sizes, int n_in,
                              void* d_out, int out_size) {
    const float* x    = (const float*)d_in[0];
    const float* mask = (const float*)d_in[1];
    const float* W    = (const float*)d_in[2];
    const float* b    = (const float*)d_in[3];
    fnet_kernel<<<1024, 256>>>(x, mask, W, b, (float*)d_out);
}